// round 1
// baseline (speedup 1.0000x reference)
#include <cuda_runtime.h>
#include <math.h>

// Problem constants (fixed by setup_inputs): B=1, L=8192, H=16, D=64
#define H 16
#define D 64
#define L 8192
#define M 128      // L / BLKQ
#define NBLK 256   // L / BLKK
#define T 25       // int(0.1 * 256)
#define NCH 16     // chunks for kvsum partial GEMM (512 rows each)

// -------- device scratch (no allocations allowed) --------
__device__ float g_km[H*D];
__device__ float g_pq[H*M*D];
__device__ float g_pk[H*NBLK*D];
__device__ float g_score[H*M*NBLK];
__device__ int   g_lut[H*M*T];
__device__ float g_kv_part[NCH*H*D*D];
__device__ float g_ks_part[NCH*H*D];
__device__ float g_kvsum[H*D*D];
__device__ float g_ksum[H*D];

// ================= km: per-(h,d) mean of k over L =================
__global__ __launch_bounds__(256) void km_kernel(const float* __restrict__ k) {
    int h = blockIdx.x;
    __shared__ float part[256];
    int tid = threadIdx.x;
    int d = tid & 63, sub = tid >> 6;   // 4 row-substreams
    float s = 0.f;
    for (int l = sub; l < L; l += 4) s += k[(l*H + h)*D + d];
    part[tid] = s;
    __syncthreads();
    if (tid < 64) {
        float t = part[tid] + part[tid+64] + part[tid+128] + part[tid+192];
        g_km[h*D + tid] = t * (1.0f/8192.0f);
    }
}

// ========== pooled_q [h][M][D], pooled_k (centered) [h][N][D] ==========
__global__ __launch_bounds__(64) void pooled_kernel(const float* __restrict__ q,
                                                    const float* __restrict__ k) {
    int h = blockIdx.x, y = blockIdx.y, d = threadIdx.x;
    if (y < M) {
        float s = 0.f;
        for (int i = 0; i < 64; i++) s += q[((y*64 + i)*H + h)*D + d];
        g_pq[(h*M + y)*D + d] = s * (1.0f/64.0f);
    } else {
        int n = y - M;
        float s = 0.f;
        for (int i = 0; i < 32; i++) s += k[((n*32 + i)*H + h)*D + d];
        g_pk[(h*NBLK + n)*D + d] = s * (1.0f/32.0f) - g_km[h*D + d];
    }
}

// ============ routing scores: score[h][m][n] = pq . pk ============
__global__ __launch_bounds__(256) void score_kernel() {
    int h = blockIdx.x, m = blockIdx.y;
    __shared__ float pq[64];
    int tid = threadIdx.x;
    if (tid < 64) pq[tid] = g_pq[(h*M + m)*D + tid];
    __syncthreads();
    int n = tid;  // 256 threads
    const float4* pk = (const float4*)(g_pk + (h*NBLK + n)*D);
    float s = 0.f;
    #pragma unroll
    for (int dd = 0; dd < 16; dd++) {
        float4 kv = pk[dd];
        s += pq[dd*4+0]*kv.x + pq[dd*4+1]*kv.y + pq[dd*4+2]*kv.z + pq[dd*4+3]*kv.w;
    }
    g_score[(h*M + m)*NBLK + n] = s;
}

// ============ top-25 per (h,m), ties -> lowest index, sorted ascending ============
__global__ __launch_bounds__(256) void topk_kernel() {
    int h = blockIdx.x;
    int w = threadIdx.x >> 5, lane = threadIdx.x & 31;
    int m = blockIdx.y*8 + w;
    const float* row = g_score + (h*M + m)*NBLK;
    float v[8];
    #pragma unroll
    for (int j = 0; j < 8; j++) v[j] = row[j*32 + lane];
    int sel[T];
    for (int t = 0; t < T; t++) {
        float bv = -INFINITY; int bi = 1 << 30;
        #pragma unroll
        for (int j = 0; j < 8; j++) {
            if (v[j] > bv) { bv = v[j]; bi = j*32 + lane; }  // strict > : lowest index kept
        }
        #pragma unroll
        for (int off = 16; off > 0; off >>= 1) {
            float ov = __shfl_xor_sync(0xffffffffu, bv, off);
            int   oi = __shfl_xor_sync(0xffffffffu, bi, off);
            if (ov > bv || (ov == bv && oi < bi)) { bv = ov; bi = oi; }
        }
        sel[t] = bi;
        if ((bi & 31) == lane) v[bi >> 5] = -INFINITY;
    }
    if (lane == 0) {
        for (int a = 1; a < T; a++) {
            int key = sel[a]; int b = a - 1;
            while (b >= 0 && sel[b] > key) { sel[b+1] = sel[b]; b--; }
            sel[b+1] = key;
        }
        for (int t = 0; t < T; t++) g_lut[(h*M + m)*T + t] = sel[t];
    }
}

// ============ block-sparse attention, writes o_s to out ([l][h][d]) ============
__global__ __launch_bounds__(256) void sparse_attn_kernel(
    const float* __restrict__ q, const float* __restrict__ k,
    const float* __restrict__ v, float* __restrict__ out)
{
    int h = blockIdx.x, m = blockIdx.y;
    __shared__ float qs[64][68];
    __shared__ float ks[32][68];
    __shared__ float vs[32][68];
    __shared__ float ps[8][8][32];
    __shared__ float kmS[64];
    int tid = threadIdx.x;
    int w = tid >> 5, lane = tid & 31;
    if (tid < 64) kmS[tid] = g_km[h*D + tid];
    for (int i = tid; i < 64*64; i += 256) {
        int r = i >> 6, d = i & 63;
        qs[r][d] = q[((m*64 + r)*H + h)*D + d];
    }
    float mrow[8], lrow[8];
    float2 acc[8];
    #pragma unroll
    for (int j = 0; j < 8; j++) { mrow[j] = -INFINITY; lrow[j] = 0.f; acc[j] = make_float2(0.f, 0.f); }

    for (int t = 0; t < T; t++) {
        int n = g_lut[(h*M + m)*T + t];
        __syncthreads();   // protect previous-iter smem reads AND q-tile write (1st iter w/ barrier below)
        for (int i = tid; i < 32*64; i += 256) {
            int r = i >> 6, d = i & 63;
            int l = n*32 + r;
            ks[r][d] = k[(l*H + h)*D + d] - kmS[d];
            vs[r][d] = v[(l*H + h)*D + d];
        }
        __syncthreads();

        // scores: lane = key within block, register-blocked over 8 queries
        float s[8];
        #pragma unroll
        for (int j = 0; j < 8; j++) s[j] = 0.f;
        const float4* krow = (const float4*)(&ks[lane][0]);
        #pragma unroll
        for (int dd = 0; dd < 16; dd++) {
            float4 kv = krow[dd];
            #pragma unroll
            for (int j = 0; j < 8; j++) {
                float4 qv = *(const float4*)(&qs[w*8 + j][dd*4]);
                s[j] += qv.x*kv.x + qv.y*kv.y + qv.z*kv.z + qv.w*kv.w;
            }
        }
        // online softmax per query
        #pragma unroll
        for (int j = 0; j < 8; j++) {
            float sj = s[j] * 0.125f;   // 1/sqrt(64)
            float bm = sj;
            #pragma unroll
            for (int o = 16; o > 0; o >>= 1) bm = fmaxf(bm, __shfl_xor_sync(0xffffffffu, bm, o));
            float mnew  = fmaxf(mrow[j], bm);
            float alpha = __expf(mrow[j] - mnew);   // 0 on first block (exp(-inf))
            float p     = __expf(sj - mnew);
            float psum  = p;
            #pragma unroll
            for (int o = 16; o > 0; o >>= 1) psum += __shfl_xor_sync(0xffffffffu, psum, o);
            lrow[j] = lrow[j]*alpha + psum;
            mrow[j] = mnew;
            acc[j].x *= alpha; acc[j].y *= alpha;
            ps[w][j][lane] = p;
        }
        __syncwarp();
        // PV: one V smem read serves 8 queries; lane owns d = {2*lane, 2*lane+1}
        #pragma unroll
        for (int kk = 0; kk < 32; kk++) {
            float2 vv = *(const float2*)(&vs[kk][2*lane]);
            #pragma unroll
            for (int j = 0; j < 8; j++) {
                float p = ps[w][j][kk];
                acc[j].x += p*vv.x; acc[j].y += p*vv.y;
            }
        }
    }
    #pragma unroll
    for (int j = 0; j < 8; j++) {
        int l = m*64 + w*8 + j;
        float inv = 1.f / lrow[j];
        float2 o2 = make_float2(acc[j].x*inv, acc[j].y*inv);
        *(float2*)(out + (l*H + h)*D + 2*lane) = o2;
    }
}

// ====== kvsum partials: kv[h][d][e] = sum_l softmax_d(k[l,h,:])[d] * v[l,h,e] ======
__global__ __launch_bounds__(256) void kvsum_partial_kernel(const float* __restrict__ k,
                                                            const float* __restrict__ v) {
    int h = blockIdx.x, c = blockIdx.y;   // NCH chunks of 512 rows
    __shared__ float kfS[8][64];
    __shared__ float vS[8][64];
    int tid = threadIdx.x, w = tid >> 5, lane = tid & 31;
    int e = tid & 63, g = tid >> 6;       // 4 d-groups of 16
    int d0 = g * 16;
    float acc[16];
    #pragma unroll
    for (int j = 0; j < 16; j++) acc[j] = 0.f;
    float ks_acc = 0.f;

    for (int sIt = 0; sIt < 64; sIt++) {
        int l = c*512 + sIt*8 + w;
        __syncthreads();
        const float* kr = k + (l*H + h)*D;
        const float* vr = v + (l*H + h)*D;
        float k0 = kr[lane], k1 = kr[lane + 32];
        float mx = fmaxf(k0, k1);
        #pragma unroll
        for (int o = 16; o > 0; o >>= 1) mx = fmaxf(mx, __shfl_xor_sync(0xffffffffu, mx, o));
        float e0 = __expf(k0 - mx), e1 = __expf(k1 - mx);
        float sm = e0 + e1;
        #pragma unroll
        for (int o = 16; o > 0; o >>= 1) sm += __shfl_xor_sync(0xffffffffu, sm, o);
        float inv = 1.f / sm;
        kfS[w][lane] = e0*inv; kfS[w][lane+32] = e1*inv;
        vS[w][lane] = vr[lane]; vS[w][lane+32] = vr[lane+32];
        __syncthreads();
        #pragma unroll
        for (int r = 0; r < 8; r++) {
            float ve = vS[r][e];
            #pragma unroll
            for (int j = 0; j < 16; j++) acc[j] += kfS[r][d0 + j] * ve;
        }
        if (g == 0) {
            #pragma unroll
            for (int r = 0; r < 8; r++) ks_acc += kfS[r][e];
        }
    }
    float* dst = g_kv_part + (c*H + h)*D*D;
    #pragma unroll
    for (int j = 0; j < 16; j++) dst[(d0 + j)*D + e] = acc[j];
    if (g == 0) g_ks_part[(c*H + h)*D + e] = ks_acc;
}

__global__ __launch_bounds__(256) void reduce_kv_kernel() {
    int h = blockIdx.x;
    for (int i = threadIdx.x; i < D*D; i += 256) {
        float s = 0.f;
        for (int c = 0; c < NCH; c++) s += g_kv_part[(c*H + h)*D*D + i];
        g_kvsum[h*D*D + i] = s;
    }
    for (int i = threadIdx.x; i < D; i += 256) {
        float s = 0.f;
        for (int c = 0; c < NCH; c++) s += g_ks_part[(c*H + h)*D + i];
        g_ksum[h*D + i] = s;
    }
}

// ======== linear branch output: out += (q_fm @ kvsum / denom) @ W^T + b ========
__global__ __launch_bounds__(256) void linear_out_kernel(const float* __restrict__ q,
                                                         const float* __restrict__ W,
                                                         const float* __restrict__ b,
                                                         float* __restrict__ out) {
    int h = blockIdx.x, chunk = blockIdx.y;  // 64 chunks of 128 rows
    __shared__ float kvS[64][64];
    __shared__ float WS[64][65];
    __shared__ float ksS[64];
    __shared__ float bS[64];
    __shared__ float qfmS[8][64];
    __shared__ float tmpS[8][64];
    int tid = threadIdx.x, w = tid >> 5, lane = tid & 31;
    for (int i = tid; i < 4096; i += 256) kvS[i >> 6][i & 63] = g_kvsum[h*D*D + i];
    for (int i = tid; i < 4096; i += 256) WS[i >> 6][i & 63] = W[i];
    if (tid < 64) { ksS[tid] = g_ksum[h*D + tid]; bS[tid] = b[tid]; }
    __syncthreads();

    for (int rr = 0; rr < 16; rr++) {
        int l = chunk*128 + rr*8 + w;
        const float* qr = q + (l*H + h)*D;
        float q0 = qr[lane], q1 = qr[lane + 32];
        float mx = fmaxf(q0, q1);
        #pragma unroll
        for (int o = 16; o > 0; o >>= 1) mx = fmaxf(mx, __shfl_xor_sync(0xffffffffu, mx, o));
        float e0 = __expf(q0 - mx), e1 = __expf(q1 - mx);
        float ssum = e0 + e1;
        #pragma unroll
        for (int o = 16; o > 0; o >>= 1) ssum += __shfl_xor_sync(0xffffffffu, ssum, o);
        float inv = 1.f / ssum;
        float f0 = e0*inv, f1 = e1*inv;
        qfmS[w][lane] = f0; qfmS[w][lane+32] = f1;
        float dn = f0*ksS[lane] + f1*ksS[lane+32];
        #pragma unroll
        for (int o = 16; o > 0; o >>= 1) dn += __shfl_xor_sync(0xffffffffu, dn, o);
        dn += 1e-6f;
        __syncwarp();
        float t0 = 0.f, t1 = 0.f;
        #pragma unroll
        for (int d = 0; d < 64; d++) {
            float qf = qfmS[w][d];
            t0 += qf * kvS[d][lane];
            t1 += qf * kvS[d][lane + 32];
        }
        float invdn = 1.f / dn;
        tmpS[w][lane] = t0*invdn; tmpS[w][lane+32] = t1*invdn;
        __syncwarp();
        float o0 = bS[lane], o1 = bS[lane + 32];
        #pragma unroll
        for (int e = 0; e < 64; e++) {
            float tv = tmpS[w][e];
            o0 += tv * WS[lane][e];
            o1 += tv * WS[lane + 32][e];
        }
        float* op = out + (l*H + h)*D;
        op[lane]      += o0;
        op[lane + 32] += o1;
    }
}

extern "C" void kernel_launch(void* const* d_in, const int* in_sizes, int n_in,
                              void* d_out, int out_size) {
    const float* q = (const float*)d_in[0];
    const float* k = (const float*)d_in[1];
    const float* v = (const float*)d_in[2];
    const float* W = (const float*)d_in[3];
    const float* b = (const float*)d_in[4];
    float* out = (float*)d_out;

    km_kernel<<<H, 256>>>(k);
    pooled_kernel<<<dim3(H, M + NBLK), 64>>>(q, k);
    score_kernel<<<dim3(H, M), 256>>>();
    topk_kernel<<<dim3(H, M/8), 256>>>();
    sparse_attn_kernel<<<dim3(H, M), 256>>>(q, k, v, out);
    kvsum_partial_kernel<<<dim3(H, NCH), 256>>>(k, v);
    reduce_kv_kernel<<<H, 256>>>();
    linear_out_kernel<<<dim3(H, 64), 256>>>(q, W, b, out);
}